// round 9
// baseline (speedup 1.0000x reference)
#include <cuda_runtime.h>
#include <cuda_fp16.h>
#include <cstdint>

#define BB 32
#define SS 128
#define UU 256
#define HH 128
#define VV 30001
#define NT_N 469             // n tiles of 64 (469*64 = 30016 >= 30001)
#define NT_M 32              // m tiles of 128

__device__ __half   g_outs[BB * SS * HH];     // RNN outputs [4096][128], fp16
__device__ uint32_t g_wsB[NT_N * 4096];       // per-tile B images: fp16x2 words, linear frag layout

// ---------------------------------------------------------------------------
__device__ __forceinline__ uint32_t smem_u32(const void* p) {
    uint32_t a;
    asm("{ .reg .u64 t; cvta.to.shared.u64 t, %1; cvt.u32.u64 %0, t; }" : "=r"(a) : "l"(p));
    return a;
}
#define CP_ASYNC16(s, g) \
    asm volatile("cp.async.cg.shared.global [%0], [%1], 16;" :: "r"(s), "l"(g) : "memory")
#define CP_COMMIT()  asm volatile("cp.async.commit_group;" ::: "memory")
#define CP_WAIT1()   asm volatile("cp.async.wait_group 1;" ::: "memory")
#define CP_WAIT0()   asm volatile("cp.async.wait_group 0;" ::: "memory")

#define LDS128U(r0, r1, r2, r3, addr) \
    asm volatile("ld.shared.v4.u32 {%0,%1,%2,%3}, [%4];" \
                 : "=r"(r0), "=r"(r1), "=r"(r2), "=r"(r3) : "r"(addr))

__device__ __forceinline__ void mma_f16(float* d, const uint32_t* a, uint32_t b0, uint32_t b1) {
    asm volatile("mma.sync.aligned.m16n8k16.row.col.f32.f16.f16.f32 "
                 "{%0,%1,%2,%3}, {%4,%5,%6,%7}, {%8,%9}, {%0,%1,%2,%3};"
                 : "+f"(d[0]), "+f"(d[1]), "+f"(d[2]), "+f"(d[3])
                 : "r"(a[0]), "r"(a[1]), "r"(a[2]), "r"(a[3]), "r"(b0), "r"(b1));
}

// ---------------------------------------------------------------------------
// prep: build g_wsB. One CTA per 64-col n-tile. 256 threads.
// Word index Wd = blk*128 + l*4 + w4, blk = nf*4 + ksp (nf:0..7, ksp:0..3).
// Contents for lane l, word w4: fp16x2 {B[kb][n], B[kb+1][n]},
//   n = nf*8 + (l>>2),  kb = 32*ksp + 2*(l&3) + 8*w4.
// ---------------------------------------------------------------------------
__global__ __launch_bounds__(256, 4)
void prep_ws(const float* __restrict__ ws)
{
    __shared__ float t[128][65];
    const int nt  = blockIdx.x;
    const int tid = threadIdx.x;
    const int n0  = nt * 64;

    for (int idx = tid; idx < 8192; idx += 256) {
        int k = idx >> 6, j = idx & 63;
        int n = n0 + j;
        t[k][j] = (n < VV) ? ws[(size_t)k * VV + n] : 0.f;
    }
    __syncthreads();

    uint32_t* dst = g_wsB + (size_t)nt * 4096;
    for (int Wd = tid; Wd < 4096; Wd += 256) {
        int w4  = Wd & 3;
        int l   = (Wd >> 2) & 31;
        int blk = Wd >> 7;
        int nf  = blk >> 2, ksp = blk & 3;
        int n   = nf * 8 + (l >> 2);
        int kb  = 32 * ksp + 2 * (l & 3) + 8 * w4;
        __half2 h = __floats2half2_rn(t[kb][n], t[kb + 1][n]);
        dst[Wd] = *(const uint32_t*)&h;
    }
}

// ---------------------------------------------------------------------------
// RNN: one CTA per batch, 384 threads, state in smem, W columns in registers,
// next-step P rows prefetched one iteration ahead. Outputs stored fp16.
// ---------------------------------------------------------------------------
__global__ __launch_bounds__(384, 1)
void rnn_kernel(const int* __restrict__ users, const int* __restrict__ items,
                const float* __restrict__ h0,
                const float* __restrict__ P_ru, const float* __restrict__ W_ru,
                const float* __restrict__ b_ru,
                const float* __restrict__ P_c, const float* __restrict__ W_c,
                const float* __restrict__ b_c)
{
    extern __shared__ float sm[];
    float* state_s = sm;
    float* rh_s    = sm + UU * HH;
    float* z_s     = rh_s + HH;
    int*   users_s = (int*)(z_s + HH);
    int*   items_s = users_s + SS;

    const int b   = blockIdx.x;
    const int tid = threadIdx.x;

    for (int t = tid; t < SS; t += blockDim.x) {
        users_s[t] = users[b * SS + t];
        items_s[t] = items[b * SS + t];
    }
    {
        const float4* src = (const float4*)(h0 + (size_t)b * UU * HH);
        float4* dst = (float4*)state_s;
        for (int i = tid; i < UU * HH / 4; i += blockDim.x) dst[i] = src[i];
    }

    float wreg[HH];
    float breg;
    if (tid < 2 * HH) {
        #pragma unroll
        for (int k = 0; k < HH; k++) wreg[k] = W_ru[k * (2 * HH) + tid];
        breg = b_ru[tid];
    } else {
        const int j = tid - 2 * HH;
        #pragma unroll
        for (int k = 0; k < HH; k++) wreg[k] = W_c[k * HH + j];
        breg = b_c[j];
    }
    __syncthreads();

    float pA;
    {
        int it0 = items_s[0];
        pA = (tid < 2 * HH) ? P_ru[(size_t)it0 * (2 * HH) + tid]
                            : P_c[(size_t)it0 * HH + (tid - 2 * HH)];
    }

    for (int t = 0; t < SS; t++) {
        const int u = users_s[t];
        const int itn = items_s[(t + 1) & (SS - 1)];
        float pN = (tid < 2 * HH) ? P_ru[(size_t)itn * (2 * HH) + tid]
                                  : P_c[(size_t)itn * HH + (tid - 2 * HH)];

        if (tid < 2 * HH) {
            const float* hs = state_s + u * HH;
            float a0 = 0.f, a1 = 0.f, a2 = 0.f, a3 = 0.f;
            float a4 = 0.f, a5 = 0.f, a6 = 0.f, a7 = 0.f;
            #pragma unroll
            for (int k = 0; k < HH; k += 8) {
                float4 h4 = *(const float4*)(hs + k);
                float4 h5 = *(const float4*)(hs + k + 4);
                a0 += h4.x * wreg[k];     a1 += h4.y * wreg[k + 1];
                a2 += h4.z * wreg[k + 2]; a3 += h4.w * wreg[k + 3];
                a4 += h5.x * wreg[k + 4]; a5 += h5.y * wreg[k + 5];
                a6 += h5.z * wreg[k + 6]; a7 += h5.w * wreg[k + 7];
            }
            float x = pA + breg + ((a0 + a1) + (a2 + a3)) + ((a4 + a5) + (a6 + a7));
            float sgm = 1.f / (1.f + __expf(-x));
            if (tid < HH) rh_s[tid] = sgm * hs[tid];
            else          z_s[tid - HH] = sgm;
        }
        __syncthreads();

        if (tid >= 2 * HH) {
            const int j = tid - 2 * HH;
            float a0 = 0.f, a1 = 0.f, a2 = 0.f, a3 = 0.f;
            float a4 = 0.f, a5 = 0.f, a6 = 0.f, a7 = 0.f;
            #pragma unroll
            for (int k = 0; k < HH; k += 8) {
                float4 r4 = *(const float4*)(rh_s + k);
                float4 r5 = *(const float4*)(rh_s + k + 4);
                a0 += r4.x * wreg[k];     a1 += r4.y * wreg[k + 1];
                a2 += r4.z * wreg[k + 2]; a3 += r4.w * wreg[k + 3];
                a4 += r5.x * wreg[k + 4]; a5 += r5.y * wreg[k + 5];
                a6 += r5.z * wreg[k + 6]; a7 += r5.w * wreg[k + 7];
            }
            float x = pA + breg + ((a0 + a1) + (a2 + a3)) + ((a4 + a5) + (a6 + a7));
            float c = tanhf(x);
            float h_old = state_s[u * HH + j];
            float z = z_s[j];
            float hn = z * h_old + (1.f - z) * c;
            state_s[u * HH + j] = hn;
            g_outs[((size_t)b * SS + t) * HH + j] = __float2half(hn);
        }
        __syncthreads();
        pA = pN;
    }
}

// ---------------------------------------------------------------------------
// Persistent GEMM (fp16 in, f32 acc): out[4096,30001] = g_outs @ ws
// 444 CTAs (3/SM) x 256 threads. CTA tile 128M x 64N, warp tile 16M x 64N.
// B: 3-stage 16KB ring via cp.async; one __syncthreads per tile.
// Inner loop: 32 x (1 LDS.128 + 2 HMMA.16816), depth-1 ping-pong b-prefetch.
// ---------------------------------------------------------------------------
#define BS_BYTES  16384
#define GEMM_SMEM (3 * BS_BYTES)     // 48KB/CTA -> 3 CTAs/SM
#define GRID_G 444

__device__ __forceinline__ void stage_B(uint32_t sbuf, int nt, int tid) {
    const uint32_t* src = g_wsB + (size_t)nt * 4096;
    #pragma unroll
    for (int jj = 0; jj < 4; jj++) {
        int ch = tid + jj * 256;
        CP_ASYNC16(sbuf + ch * 16, src + ch * 4);
    }
}

// A fragments (m16n8k16 row-major), direct u32 loads from fp16 g_outs.
__device__ __forceinline__ void load_a(uint32_t a[8][4], int mt, int w, int l) {
    const __half* A0 = g_outs + (size_t)(mt * 128 + w * 16 + (l >> 2)) * HH;
    const __half* A1 = A0 + 8 * HH;
    #pragma unroll
    for (int ks = 0; ks < 8; ks++) {
        int k0 = 16 * ks + 2 * (l & 3);
        a[ks][0] = *(const uint32_t*)(A0 + k0);
        a[ks][1] = *(const uint32_t*)(A1 + k0);
        a[ks][2] = *(const uint32_t*)(A0 + k0 + 8);
        a[ks][3] = *(const uint32_t*)(A1 + k0 + 8);
    }
}

__global__ __launch_bounds__(256, 3)
void gemm_kernel(float* __restrict__ out)
{
    extern __shared__ uint32_t smu[];
    const int tid = threadIdx.x;
    const int w = tid >> 5, l = tid & 31;
    const uint32_t sbase = smem_u32(smu);

    const int cta = blockIdx.x;
    // 15008 tiles = 444*33 + 356 -> first 356 CTAs take 34
    int t0  = cta * 33 + (cta < 356 ? cta : 356);
    int cnt = 33 + (cta < 356 ? 1 : 0);
    int mt = t0 / NT_N;
    int nt = t0 - mt * NT_N;

    stage_B(sbase, nt, tid);
    CP_COMMIT();

    uint32_t a[8][4];
    load_a(a, mt, w, l);

    const int c = l & 3, r = l >> 2;

    for (int i = 0; i < cnt; i++) {
        const int j = i + 1;
        const bool have_next = (j < cnt);
        int mt_j = mt, nt_j = nt + 1;
        if (nt_j == NT_N) { nt_j = 0; mt_j++; }

        if (have_next) {
            stage_B(sbase + (uint32_t)(j % 3) * BS_BYTES, nt_j, tid);
            CP_COMMIT();
            CP_WAIT1();
        } else {
            CP_WAIT0();
        }
        __syncthreads();     // single barrier per tile (3-stage ring -> safe)

        float acc[8][4];
        #pragma unroll
        for (int nf = 0; nf < 8; nf++) {
            acc[nf][0] = 0.f; acc[nf][1] = 0.f; acc[nf][2] = 0.f; acc[nf][3] = 0.f;
        }

        // per-thread base: lane stride 16B inside each 512B (nf,ksp) block
        const uint32_t Bt = sbase + (uint32_t)(i % 3) * BS_BYTES + (uint32_t)l * 16;
        // it order: ksp = it>>3 (slow), nf = it&7 (fast); block addr = (nf*4+ksp)*512
        uint32_t b0[4], b1[4];
        LDS128U(b0[0], b0[1], b0[2], b0[3], Bt);               // it=0: nf0 ksp0
        #pragma unroll
        for (int it = 0; it < 32; it++) {
            uint32_t* cur = (it & 1) ? b1 : b0;
            uint32_t* nxt = (it & 1) ? b0 : b1;
            if (it < 31) {
                const int i1 = it + 1;
                const uint32_t ba = (uint32_t)(((i1 & 7) * 4 + (i1 >> 3)) * 512);
                LDS128U(nxt[0], nxt[1], nxt[2], nxt[3], Bt + ba);
            }
            const int ksp = it >> 3, nf = it & 7;
            mma_f16(acc[nf], a[2 * ksp],     cur[0], cur[1]);
            mma_f16(acc[nf], a[2 * ksp + 1], cur[2], cur[3]);
        }

        // epilogue: registers -> gmem
        {
            size_t r0 = (size_t)(mt * 128 + w * 16 + r) * VV;
            size_t r1 = r0 + (size_t)8 * VV;
            int colb = nt * 64 + c * 2;
            if (nt < NT_N - 1) {
                #pragma unroll
                for (int nf = 0; nf < 8; nf++) {
                    int cc = colb + nf * 8;
                    out[r0 + cc]     = acc[nf][0];
                    out[r0 + cc + 1] = acc[nf][1];
                    out[r1 + cc]     = acc[nf][2];
                    out[r1 + cc + 1] = acc[nf][3];
                }
            } else {
                #pragma unroll
                for (int nf = 0; nf < 8; nf++) {
                    int cc = colb + nf * 8;
                    if (cc < VV)     { out[r0 + cc]     = acc[nf][0]; out[r1 + cc]     = acc[nf][2]; }
                    if (cc + 1 < VV) { out[r0 + cc + 1] = acc[nf][1]; out[r1 + cc + 1] = acc[nf][3]; }
                }
            }
        }

        if (have_next && mt_j != mt) load_a(a, mt_j, w, l);
        mt = mt_j; nt = nt_j;
    }
}

// ---------------------------------------------------------------------------
#define RNN_SMEM ((UU * HH + 2 * HH) * 4 + 2 * SS * 4)

extern "C" void kernel_launch(void* const* d_in, const int* in_sizes, int n_in,
                              void* d_out, int out_size)
{
    const int*   users = (const int*)d_in[0];
    const int*   items = (const int*)d_in[1];
    const float* h0    = (const float*)d_in[2];
    const float* P_ru  = (const float*)d_in[3];
    const float* W_ru  = (const float*)d_in[4];
    const float* b_ru  = (const float*)d_in[5];
    const float* P_c   = (const float*)d_in[6];
    const float* W_c   = (const float*)d_in[7];
    const float* b_c   = (const float*)d_in[8];
    const float* ws    = (const float*)d_in[9];
    float* out = (float*)d_out;

    static int attr_done = 0;
    if (!attr_done) {
        cudaFuncSetAttribute(rnn_kernel,  cudaFuncAttributeMaxDynamicSharedMemorySize, RNN_SMEM);
        cudaFuncSetAttribute(gemm_kernel, cudaFuncAttributeMaxDynamicSharedMemorySize, GEMM_SMEM);
        attr_done = 1;
    }

    prep_ws<<<NT_N, 256>>>(ws);
    rnn_kernel<<<BB, 384, RNN_SMEM>>>(users, items, h0, P_ru, W_ru, b_ru, P_c, W_c, b_c);
    gemm_kernel<<<GRID_G, 256, GEMM_SMEM>>>(out);
}

// round 10
// speedup vs baseline: 1.0405x; 1.0405x over previous
#include <cuda_runtime.h>
#include <cuda_fp16.h>
#include <cstdint>

#define BB 32
#define SS 128
#define UU 256
#define HH 128
#define VV 30001
#define NT_N 469             // n tiles of 64 (469*64 = 30016 >= 30001)
#define NT_M 32              // m tiles of 128

__device__ __half   g_outs[BB * SS * HH];     // RNN outputs [4096][128], fp16
__device__ uint32_t g_wsB[NT_N * 4096];       // per-tile B images: fp16x2 words, linear frag layout

// ---------------------------------------------------------------------------
__device__ __forceinline__ uint32_t smem_u32(const void* p) {
    uint32_t a;
    asm("{ .reg .u64 t; cvta.to.shared.u64 t, %1; cvt.u32.u64 %0, t; }" : "=r"(a) : "l"(p));
    return a;
}
#define CP_ASYNC16(s, g) \
    asm volatile("cp.async.cg.shared.global [%0], [%1], 16;" :: "r"(s), "l"(g) : "memory")
#define CP_COMMIT()  asm volatile("cp.async.commit_group;" ::: "memory")
#define CP_WAIT1()   asm volatile("cp.async.wait_group 1;" ::: "memory")
#define CP_WAIT0()   asm volatile("cp.async.wait_group 0;" ::: "memory")

#define LDS128U(r0, r1, r2, r3, addr) \
    asm volatile("ld.shared.v4.u32 {%0,%1,%2,%3}, [%4];" \
                 : "=r"(r0), "=r"(r1), "=r"(r2), "=r"(r3) : "r"(addr))

__device__ __forceinline__ void mma_f16(float* d, const uint32_t* a, uint32_t b0, uint32_t b1) {
    asm volatile("mma.sync.aligned.m16n8k16.row.col.f32.f16.f16.f32 "
                 "{%0,%1,%2,%3}, {%4,%5,%6,%7}, {%8,%9}, {%0,%1,%2,%3};"
                 : "+f"(d[0]), "+f"(d[1]), "+f"(d[2]), "+f"(d[3])
                 : "r"(a[0]), "r"(a[1]), "r"(a[2]), "r"(a[3]), "r"(b0), "r"(b1));
}

// ---------------------------------------------------------------------------
// Fused kernel: CTAs [0,32) run the RNN (one per batch);
// CTAs [32, 32+469) build one 64-col pre-fragmented fp16 B tile of g_wsB.
//
// B image: word Wd = blk*128 + l*4 + w4, blk = nf*4 + ksp.
//   fp16x2 {B[kb][n], B[kb+1][n]}, n = nf*8 + (l>>2), kb = 32*ksp + 2*(l&3) + 8*w4.
// ---------------------------------------------------------------------------
__global__ __launch_bounds__(384, 1)
void rnn_prep_kernel(const int* __restrict__ users, const int* __restrict__ items,
                     const float* __restrict__ h0,
                     const float* __restrict__ P_ru, const float* __restrict__ W_ru,
                     const float* __restrict__ b_ru,
                     const float* __restrict__ P_c, const float* __restrict__ W_c,
                     const float* __restrict__ b_c,
                     const float* __restrict__ ws)
{
    extern __shared__ float sm[];
    const int tid = threadIdx.x;

    if (blockIdx.x >= BB) {
        // ---------------- ws tile prep ----------------
        const int nt = blockIdx.x - BB;
        float (*t)[65] = (float(*)[65])sm;
        const int n0 = nt * 64;

        for (int idx = tid; idx < 8192; idx += 384) {
            int k = idx >> 6, j = idx & 63;
            int n = n0 + j;
            t[k][j] = (n < VV) ? ws[(size_t)k * VV + n] : 0.f;
        }
        __syncthreads();

        uint32_t* dst = g_wsB + (size_t)nt * 4096;
        for (int Wd = tid; Wd < 4096; Wd += 384) {
            int w4  = Wd & 3;
            int l   = (Wd >> 2) & 31;
            int blk = Wd >> 7;
            int nf  = blk >> 2, ksp = blk & 3;
            int n   = nf * 8 + (l >> 2);
            int kb  = 32 * ksp + 2 * (l & 3) + 8 * w4;
            __half2 h = __floats2half2_rn(t[kb][n], t[kb + 1][n]);
            dst[Wd] = *(const uint32_t*)&h;
        }
        return;
    }

    // ---------------- RNN ----------------
    float* state_s = sm;
    float* rh_s    = sm + UU * HH;
    float* z_s     = rh_s + HH;
    int*   users_s = (int*)(z_s + HH);
    int*   items_s = users_s + SS;

    const int b = blockIdx.x;

    for (int t = tid; t < SS; t += blockDim.x) {
        users_s[t] = users[b * SS + t];
        items_s[t] = items[b * SS + t];
    }
    {
        const float4* src = (const float4*)(h0 + (size_t)b * UU * HH);
        float4* dst = (float4*)state_s;
        for (int i = tid; i < UU * HH / 4; i += blockDim.x) dst[i] = src[i];
    }

    float wreg[HH];
    float breg;
    if (tid < 2 * HH) {
        #pragma unroll
        for (int k = 0; k < HH; k++) wreg[k] = W_ru[k * (2 * HH) + tid];
        breg = b_ru[tid];
    } else {
        const int j = tid - 2 * HH;
        #pragma unroll
        for (int k = 0; k < HH; k++) wreg[k] = W_c[k * HH + j];
        breg = b_c[j];
    }
    __syncthreads();

    float pA;
    {
        int it0 = items_s[0];
        pA = (tid < 2 * HH) ? P_ru[(size_t)it0 * (2 * HH) + tid]
                            : P_c[(size_t)it0 * HH + (tid - 2 * HH)];
    }

    for (int t = 0; t < SS; t++) {
        const int u = users_s[t];
        const int itn = items_s[(t + 1) & (SS - 1)];
        float pN = (tid < 2 * HH) ? P_ru[(size_t)itn * (2 * HH) + tid]
                                  : P_c[(size_t)itn * HH + (tid - 2 * HH)];

        if (tid < 2 * HH) {
            const float* hs = state_s + u * HH;
            float a0 = 0.f, a1 = 0.f, a2 = 0.f, a3 = 0.f;
            float a4 = 0.f, a5 = 0.f, a6 = 0.f, a7 = 0.f;
            #pragma unroll
            for (int k = 0; k < HH; k += 8) {
                float4 h4 = *(const float4*)(hs + k);
                float4 h5 = *(const float4*)(hs + k + 4);
                a0 += h4.x * wreg[k];     a1 += h4.y * wreg[k + 1];
                a2 += h4.z * wreg[k + 2]; a3 += h4.w * wreg[k + 3];
                a4 += h5.x * wreg[k + 4]; a5 += h5.y * wreg[k + 5];
                a6 += h5.z * wreg[k + 6]; a7 += h5.w * wreg[k + 7];
            }
            float x = pA + breg + ((a0 + a1) + (a2 + a3)) + ((a4 + a5) + (a6 + a7));
            float sgm = 1.f / (1.f + __expf(-x));
            if (tid < HH) rh_s[tid] = sgm * hs[tid];
            else          z_s[tid - HH] = sgm;
        }
        __syncthreads();

        if (tid >= 2 * HH) {
            const int j = tid - 2 * HH;
            float a0 = 0.f, a1 = 0.f, a2 = 0.f, a3 = 0.f;
            float a4 = 0.f, a5 = 0.f, a6 = 0.f, a7 = 0.f;
            #pragma unroll
            for (int k = 0; k < HH; k += 8) {
                float4 r4 = *(const float4*)(rh_s + k);
                float4 r5 = *(const float4*)(rh_s + k + 4);
                a0 += r4.x * wreg[k];     a1 += r4.y * wreg[k + 1];
                a2 += r4.z * wreg[k + 2]; a3 += r4.w * wreg[k + 3];
                a4 += r5.x * wreg[k + 4]; a5 += r5.y * wreg[k + 5];
                a6 += r5.z * wreg[k + 6]; a7 += r5.w * wreg[k + 7];
            }
            float x = pA + breg + ((a0 + a1) + (a2 + a3)) + ((a4 + a5) + (a6 + a7));
            float c = tanhf(x);
            float h_old = state_s[u * HH + j];
            float z = z_s[j];
            float hn = z * h_old + (1.f - z) * c;
            state_s[u * HH + j] = hn;
            g_outs[((size_t)b * SS + t) * HH + j] = __float2half(hn);
        }
        __syncthreads();
        pA = pN;
    }
}

// ---------------------------------------------------------------------------
// Persistent GEMM (fp16 in, f32 acc): out[4096,30001] = g_outs @ ws
// 296 CTAs (2/SM) x 256 threads. CTA tile 128M x 64N, warp tile 16M x 64N.
// B double-buffered 16KB cp.async. Inner loop per ksp-phase:
// 8 x LDS.128 then 16 independent HMMA (acc reuse distance 8).
// ---------------------------------------------------------------------------
#define BS_BYTES  16384
#define GEMM_SMEM (2 * BS_BYTES)     // 32KB/CTA
#define GRID_G 296

__device__ __forceinline__ void stage_B(uint32_t sbuf, int nt, int tid) {
    const uint32_t* src = g_wsB + (size_t)nt * 4096;
    #pragma unroll
    for (int jj = 0; jj < 4; jj++) {
        int ch = tid + jj * 256;
        CP_ASYNC16(sbuf + ch * 16, src + ch * 4);
    }
}

// A fragments (m16n8k16 row-major), direct u32 loads from fp16 g_outs.
__device__ __forceinline__ void load_a(uint32_t a[8][4], int mt, int w, int l) {
    const __half* A0 = g_outs + (size_t)(mt * 128 + w * 16 + (l >> 2)) * HH;
    const __half* A1 = A0 + 8 * HH;
    #pragma unroll
    for (int ks = 0; ks < 8; ks++) {
        int k0 = 16 * ks + 2 * (l & 3);
        a[ks][0] = *(const uint32_t*)(A0 + k0);
        a[ks][1] = *(const uint32_t*)(A1 + k0);
        a[ks][2] = *(const uint32_t*)(A0 + k0 + 8);
        a[ks][3] = *(const uint32_t*)(A1 + k0 + 8);
    }
}

__global__ __launch_bounds__(256, 2)
void gemm_kernel(float* __restrict__ out)
{
    extern __shared__ uint32_t smu[];
    const int tid = threadIdx.x;
    const int w = tid >> 5, l = tid & 31;
    const uint32_t sbase = smem_u32(smu);

    const int cta = blockIdx.x;
    // 15008 tiles = 296*50 + 208 -> first 208 CTAs take 51
    int t0  = cta * 50 + (cta < 208 ? cta : 208);
    int cnt = 50 + (cta < 208 ? 1 : 0);
    int mt = t0 / NT_N;
    int nt = t0 - mt * NT_N;

    stage_B(sbase, nt, tid);
    CP_COMMIT();

    uint32_t a[8][4];
    load_a(a, mt, w, l);

    const int c = l & 3, r = l >> 2;

    for (int i = 0; i < cnt; i++) {
        const int j = i + 1;
        const bool have_next = (j < cnt);
        int mt_j = mt, nt_j = nt + 1;
        if (nt_j == NT_N) { nt_j = 0; mt_j++; }

        if (have_next) {
            stage_B(sbase + (uint32_t)((j & 1) ? BS_BYTES : 0), nt_j, tid);
            CP_COMMIT();
            CP_WAIT1();
        } else {
            CP_WAIT0();
        }
        __syncthreads();

        float acc[8][4];
        #pragma unroll
        for (int nf = 0; nf < 8; nf++) {
            acc[nf][0] = 0.f; acc[nf][1] = 0.f; acc[nf][2] = 0.f; acc[nf][3] = 0.f;
        }

        // per-thread base: lane stride 16B inside each 512B (nf,ksp) block
        const uint32_t Bt = sbase + (uint32_t)((i & 1) ? BS_BYTES : 0) + (uint32_t)l * 16;
        #pragma unroll
        for (int ksp = 0; ksp < 4; ksp++) {
            uint32_t bf[8][4];
            #pragma unroll
            for (int nf = 0; nf < 8; nf++) {
                const uint32_t ba = (uint32_t)((nf * 4 + ksp) * 512);
                LDS128U(bf[nf][0], bf[nf][1], bf[nf][2], bf[nf][3], Bt + ba);
            }
            // 16 mma's, all independent at distance 8 (no adjacent RAW on acc)
            #pragma unroll
            for (int nf = 0; nf < 8; nf++)
                mma_f16(acc[nf], a[2 * ksp], bf[nf][0], bf[nf][1]);
            #pragma unroll
            for (int nf = 0; nf < 8; nf++)
                mma_f16(acc[nf], a[2 * ksp + 1], bf[nf][2], bf[nf][3]);
        }

        // epilogue: registers -> gmem (32B sector-aligned pair stores)
        {
            size_t r0 = (size_t)(mt * 128 + w * 16 + r) * VV;
            size_t r1 = r0 + (size_t)8 * VV;
            int colb = nt * 64 + c * 2;
            if (nt < NT_N - 1) {
                #pragma unroll
                for (int nf = 0; nf < 8; nf++) {
                    int cc = colb + nf * 8;
                    out[r0 + cc]     = acc[nf][0];
                    out[r0 + cc + 1] = acc[nf][1];
                    out[r1 + cc]     = acc[nf][2];
                    out[r1 + cc + 1] = acc[nf][3];
                }
            } else {
                #pragma unroll
                for (int nf = 0; nf < 8; nf++) {
                    int cc = colb + nf * 8;
                    if (cc < VV)     { out[r0 + cc]     = acc[nf][0]; out[r1 + cc]     = acc[nf][2]; }
                    if (cc + 1 < VV) { out[r0 + cc + 1] = acc[nf][1]; out[r1 + cc + 1] = acc[nf][3]; }
                }
            }
        }
        __syncthreads();

        if (have_next && mt_j != mt) load_a(a, mt_j, w, l);
        mt = mt_j; nt = nt_j;
    }
}

// ---------------------------------------------------------------------------
#define RNN_SMEM ((UU * HH + 2 * HH) * 4 + 2 * SS * 4)

extern "C" void kernel_launch(void* const* d_in, const int* in_sizes, int n_in,
                              void* d_out, int out_size)
{
    const int*   users = (const int*)d_in[0];
    const int*   items = (const int*)d_in[1];
    const float* h0    = (const float*)d_in[2];
    const float* P_ru  = (const float*)d_in[3];
    const float* W_ru  = (const float*)d_in[4];
    const float* b_ru  = (const float*)d_in[5];
    const float* P_c   = (const float*)d_in[6];
    const float* W_c   = (const float*)d_in[7];
    const float* b_c   = (const float*)d_in[8];
    const float* ws    = (const float*)d_in[9];
    float* out = (float*)d_out;

    static int attr_done = 0;
    if (!attr_done) {
        cudaFuncSetAttribute(rnn_prep_kernel, cudaFuncAttributeMaxDynamicSharedMemorySize, RNN_SMEM);
        cudaFuncSetAttribute(gemm_kernel, cudaFuncAttributeMaxDynamicSharedMemorySize, GEMM_SMEM);
        attr_done = 1;
    }

    rnn_prep_kernel<<<BB + NT_N, 384, RNN_SMEM>>>(users, items, h0, P_ru, W_ru, b_ru,
                                                  P_c, W_c, b_c, ws);
    gemm_kernel<<<GRID_G, 256, GEMM_SMEM>>>(out);
}

// round 11
// speedup vs baseline: 1.0584x; 1.0172x over previous
#include <cuda_runtime.h>
#include <cuda_fp16.h>
#include <cstdint>

#define BB 32
#define SS 128
#define UU 256
#define HH 128
#define VV 30001
#define NT_N 469             // n tiles of 64 (469*64 = 30016 >= 30001)
#define NT_M 32              // m tiles of 128

__device__ __half   g_outs[BB * SS * HH];     // RNN outputs [4096][128], fp16
__device__ uint32_t g_wsB[NT_N * 4096];       // per-tile B images: fp16x2 words, linear frag layout

// ---------------------------------------------------------------------------
__device__ __forceinline__ uint32_t smem_u32(const void* p) {
    uint32_t a;
    asm("{ .reg .u64 t; cvta.to.shared.u64 t, %1; cvt.u32.u64 %0, t; }" : "=r"(a) : "l"(p));
    return a;
}
#define CP_ASYNC16(s, g) \
    asm volatile("cp.async.cg.shared.global [%0], [%1], 16;" :: "r"(s), "l"(g) : "memory")
#define CP_COMMIT()  asm volatile("cp.async.commit_group;" ::: "memory")
#define CP_WAIT2()   asm volatile("cp.async.wait_group 2;" ::: "memory")

#define LDS128U(r0, r1, r2, r3, addr) \
    asm volatile("ld.shared.v4.u32 {%0,%1,%2,%3}, [%4];" \
                 : "=r"(r0), "=r"(r1), "=r"(r2), "=r"(r3) : "r"(addr))

__device__ __forceinline__ void mma_f16(float* d, const uint32_t* a, uint32_t b0, uint32_t b1) {
    asm volatile("mma.sync.aligned.m16n8k16.row.col.f32.f16.f16.f32 "
                 "{%0,%1,%2,%3}, {%4,%5,%6,%7}, {%8,%9}, {%0,%1,%2,%3};"
                 : "+f"(d[0]), "+f"(d[1]), "+f"(d[2]), "+f"(d[3])
                 : "r"(a[0]), "r"(a[1]), "r"(a[2]), "r"(a[3]), "r"(b0), "r"(b1));
}

// ---------------------------------------------------------------------------
// Fused kernel: CTAs [0,32) run the RNN (one per batch);
// CTAs [32, 32+469) build one 64-col pre-fragmented fp16 B tile of g_wsB.
// B image: word Wd = blk*128 + l*4 + w4, blk = nf*4 + ksp.
//   fp16x2 {B[kb][n], B[kb+1][n]}, n = nf*8 + (l>>2), kb = 32*ksp + 2*(l&3) + 8*w4.
// ---------------------------------------------------------------------------
__global__ __launch_bounds__(384, 1)
void rnn_prep_kernel(const int* __restrict__ users, const int* __restrict__ items,
                     const float* __restrict__ h0,
                     const float* __restrict__ P_ru, const float* __restrict__ W_ru,
                     const float* __restrict__ b_ru,
                     const float* __restrict__ P_c, const float* __restrict__ W_c,
                     const float* __restrict__ b_c,
                     const float* __restrict__ ws)
{
    extern __shared__ float sm[];
    const int tid = threadIdx.x;

    if (blockIdx.x >= BB) {
        const int nt = blockIdx.x - BB;
        float (*t)[65] = (float(*)[65])sm;
        const int n0 = nt * 64;

        for (int idx = tid; idx < 8192; idx += 384) {
            int k = idx >> 6, j = idx & 63;
            int n = n0 + j;
            t[k][j] = (n < VV) ? ws[(size_t)k * VV + n] : 0.f;
        }
        __syncthreads();

        uint32_t* dst = g_wsB + (size_t)nt * 4096;
        for (int Wd = tid; Wd < 4096; Wd += 384) {
            int w4  = Wd & 3;
            int l   = (Wd >> 2) & 31;
            int blk = Wd >> 7;
            int nf  = blk >> 2, ksp = blk & 3;
            int n   = nf * 8 + (l >> 2);
            int kb  = 32 * ksp + 2 * (l & 3) + 8 * w4;
            __half2 h = __floats2half2_rn(t[kb][n], t[kb + 1][n]);
            dst[Wd] = *(const uint32_t*)&h;
        }
        return;
    }

    // ---------------- RNN ----------------
    float* state_s = sm;
    float* rh_s    = sm + UU * HH;
    float* z_s     = rh_s + HH;
    int*   users_s = (int*)(z_s + HH);
    int*   items_s = users_s + SS;

    const int b = blockIdx.x;

    for (int t = tid; t < SS; t += blockDim.x) {
        users_s[t] = users[b * SS + t];
        items_s[t] = items[b * SS + t];
    }
    {
        const float4* src = (const float4*)(h0 + (size_t)b * UU * HH);
        float4* dst = (float4*)state_s;
        for (int i = tid; i < UU * HH / 4; i += blockDim.x) dst[i] = src[i];
    }

    float wreg[HH];
    float breg;
    if (tid < 2 * HH) {
        #pragma unroll
        for (int k = 0; k < HH; k++) wreg[k] = W_ru[k * (2 * HH) + tid];
        breg = b_ru[tid];
    } else {
        const int j = tid - 2 * HH;
        #pragma unroll
        for (int k = 0; k < HH; k++) wreg[k] = W_c[k * HH + j];
        breg = b_c[j];
    }
    __syncthreads();

    float pA;
    {
        int it0 = items_s[0];
        pA = (tid < 2 * HH) ? P_ru[(size_t)it0 * (2 * HH) + tid]
                            : P_c[(size_t)it0 * HH + (tid - 2 * HH)];
    }

    for (int t = 0; t < SS; t++) {
        const int u = users_s[t];
        const int itn = items_s[(t + 1) & (SS - 1)];
        float pN = (tid < 2 * HH) ? P_ru[(size_t)itn * (2 * HH) + tid]
                                  : P_c[(size_t)itn * HH + (tid - 2 * HH)];

        if (tid < 2 * HH) {
            const float* hs = state_s + u * HH;
            float a0 = 0.f, a1 = 0.f, a2 = 0.f, a3 = 0.f;
            float a4 = 0.f, a5 = 0.f, a6 = 0.f, a7 = 0.f;
            #pragma unroll
            for (int k = 0; k < HH; k += 8) {
                float4 h4 = *(const float4*)(hs + k);
                float4 h5 = *(const float4*)(hs + k + 4);
                a0 += h4.x * wreg[k];     a1 += h4.y * wreg[k + 1];
                a2 += h4.z * wreg[k + 2]; a3 += h4.w * wreg[k + 3];
                a4 += h5.x * wreg[k + 4]; a5 += h5.y * wreg[k + 5];
                a6 += h5.z * wreg[k + 6]; a7 += h5.w * wreg[k + 7];
            }
            float x = pA + breg + ((a0 + a1) + (a2 + a3)) + ((a4 + a5) + (a6 + a7));
            float sgm = 1.f / (1.f + __expf(-x));
            if (tid < HH) rh_s[tid] = sgm * hs[tid];
            else          z_s[tid - HH] = sgm;
        }
        __syncthreads();

        if (tid >= 2 * HH) {
            const int j = tid - 2 * HH;
            float a0 = 0.f, a1 = 0.f, a2 = 0.f, a3 = 0.f;
            float a4 = 0.f, a5 = 0.f, a6 = 0.f, a7 = 0.f;
            #pragma unroll
            for (int k = 0; k < HH; k += 8) {
                float4 r4 = *(const float4*)(rh_s + k);
                float4 r5 = *(const float4*)(rh_s + k + 4);
                a0 += r4.x * wreg[k];     a1 += r4.y * wreg[k + 1];
                a2 += r4.z * wreg[k + 2]; a3 += r4.w * wreg[k + 3];
                a4 += r5.x * wreg[k + 4]; a5 += r5.y * wreg[k + 5];
                a6 += r5.z * wreg[k + 6]; a7 += r5.w * wreg[k + 7];
            }
            float x = pA + breg + ((a0 + a1) + (a2 + a3)) + ((a4 + a5) + (a6 + a7));
            float c = tanhf(x);
            float h_old = state_s[u * HH + j];
            float z = z_s[j];
            float hn = z * h_old + (1.f - z) * c;
            state_s[u * HH + j] = hn;
            g_outs[((size_t)b * SS + t) * HH + j] = __float2half(hn);
        }
        __syncthreads();
        pA = pN;
    }
}

// ---------------------------------------------------------------------------
// Persistent GEMM (fp16 in, f32 acc): out[4096,30001] = g_outs @ ws
// 296 CTAs (2/SM) x 256 threads. CTA tile 128M x 64N, warp tile 16M x 64N.
// B: 4-stage 16KB cp.async ring (prefetch depth 3), ONE __syncthreads/tile.
// Per tile: wait(group i) -> sync -> compute+epilogue(buf i%4)
//           -> stage tile i+3 into buf (i+3)%4 -> commit.
// ---------------------------------------------------------------------------
#define BS_BYTES  16384
#define NSTAGE    4
#define GEMM_SMEM (NSTAGE * BS_BYTES)    // 64KB/CTA -> 2 CTAs/SM
#define GRID_G 296

__device__ __forceinline__ void stage_B(uint32_t sbuf, int nt, int tid) {
    const uint32_t* src = g_wsB + (size_t)nt * 4096;
    #pragma unroll
    for (int jj = 0; jj < 4; jj++) {
        int ch = tid + jj * 256;
        CP_ASYNC16(sbuf + ch * 16, src + ch * 4);
    }
}

__device__ __forceinline__ void load_a(uint32_t a[8][4], int mt, int w, int l) {
    const __half* A0 = g_outs + (size_t)(mt * 128 + w * 16 + (l >> 2)) * HH;
    const __half* A1 = A0 + 8 * HH;
    #pragma unroll
    for (int ks = 0; ks < 8; ks++) {
        int k0 = 16 * ks + 2 * (l & 3);
        a[ks][0] = *(const uint32_t*)(A0 + k0);
        a[ks][1] = *(const uint32_t*)(A1 + k0);
        a[ks][2] = *(const uint32_t*)(A0 + k0 + 8);
        a[ks][3] = *(const uint32_t*)(A1 + k0 + 8);
    }
}

__global__ __launch_bounds__(256, 2)
void gemm_kernel(float* __restrict__ out)
{
    extern __shared__ uint32_t smu[];
    const int tid = threadIdx.x;
    const int w = tid >> 5, l = tid & 31;
    const uint32_t sbase = smem_u32(smu);

    const int cta = blockIdx.x;
    // 15008 tiles = 296*50 + 208 -> first 208 CTAs take 51
    int t0  = cta * 50 + (cta < 208 ? cta : 208);
    int cnt = 50 + (cta < 208 ? 1 : 0);
    int mt = t0 / NT_N;
    int nt = t0 - mt * NT_N;

    // staging cursor (tile t0+s)
    int nt_s = nt, mt_s = mt;
    #pragma unroll
    for (int s = 0; s < NSTAGE - 1; s++) {
        if (s < cnt) stage_B(sbase + (uint32_t)s * BS_BYTES, nt_s, tid);
        CP_COMMIT();
        if (++nt_s == NT_N) { nt_s = 0; mt_s++; }
    }

    uint32_t a[8][4];
    load_a(a, mt, w, l);

    const int c = l & 3, r = l >> 2;

    for (int i = 0; i < cnt; i++) {
        CP_WAIT2();          // group for tile i complete (mine)
        __syncthreads();     // all threads' groups for tile i visible; also
                             // guarantees everyone finished compute(i-1)

        float acc[8][4];
        #pragma unroll
        for (int nf = 0; nf < 8; nf++) {
            acc[nf][0] = 0.f; acc[nf][1] = 0.f; acc[nf][2] = 0.f; acc[nf][3] = 0.f;
        }

        const uint32_t Bt = sbase + (uint32_t)(i & (NSTAGE - 1)) * BS_BYTES + (uint32_t)l * 16;
        #pragma unroll
        for (int ksp = 0; ksp < 4; ksp++) {
            uint32_t bf[8][4];
            #pragma unroll
            for (int nf = 0; nf < 8; nf++) {
                const uint32_t ba = (uint32_t)((nf * 4 + ksp) * 512);
                LDS128U(bf[nf][0], bf[nf][1], bf[nf][2], bf[nf][3], Bt + ba);
            }
            #pragma unroll
            for (int nf = 0; nf < 8; nf++)
                mma_f16(acc[nf], a[2 * ksp], bf[nf][0], bf[nf][1]);
            #pragma unroll
            for (int nf = 0; nf < 8; nf++)
                mma_f16(acc[nf], a[2 * ksp + 1], bf[nf][2], bf[nf][3]);
        }

        // epilogue: registers -> gmem
        {
            size_t r0 = (size_t)(mt * 128 + w * 16 + r) * VV;
            size_t r1 = r0 + (size_t)8 * VV;
            int colb = nt * 64 + c * 2;
            if (nt < NT_N - 1) {
                #pragma unroll
                for (int nf = 0; nf < 8; nf++) {
                    int cc = colb + nf * 8;
                    out[r0 + cc]     = acc[nf][0];
                    out[r0 + cc + 1] = acc[nf][1];
                    out[r1 + cc]     = acc[nf][2];
                    out[r1 + cc + 1] = acc[nf][3];
                }
            } else {
                #pragma unroll
                for (int nf = 0; nf < 8; nf++) {
                    int cc = colb + nf * 8;
                    if (cc < VV)     { out[r0 + cc]     = acc[nf][0]; out[r1 + cc]     = acc[nf][2]; }
                    if (cc + 1 < VV) { out[r0 + cc + 1] = acc[nf][1]; out[r1 + cc + 1] = acc[nf][3]; }
                }
            }
        }

        // stage tile i+3 (overwrites buf (i-1)%4; safe: sync above passed)
        const int s3 = i + NSTAGE - 1;
        if (s3 < cnt) stage_B(sbase + (uint32_t)(s3 & (NSTAGE - 1)) * BS_BYTES, nt_s, tid);
        CP_COMMIT();
        if (++nt_s == NT_N) { nt_s = 0; mt_s++; }

        // advance compute cursor; reload A on m-tile change
        int mt_j = mt, nt_j = nt + 1;
        if (nt_j == NT_N) { nt_j = 0; mt_j++; }
        if (i + 1 < cnt && mt_j != mt) load_a(a, mt_j, w, l);
        mt = mt_j; nt = nt_j;
    }
}

// ---------------------------------------------------------------------------
#define RNN_SMEM ((UU * HH + 2 * HH) * 4 + 2 * SS * 4)

extern "C" void kernel_launch(void* const* d_in, const int* in_sizes, int n_in,
                              void* d_out, int out_size)
{
    const int*   users = (const int*)d_in[0];
    const int*   items = (const int*)d_in[1];
    const float* h0    = (const float*)d_in[2];
    const float* P_ru  = (const float*)d_in[3];
    const float* W_ru  = (const float*)d_in[4];
    const float* b_ru  = (const float*)d_in[5];
    const float* P_c   = (const float*)d_in[6];
    const float* W_c   = (const float*)d_in[7];
    const float* b_c   = (const float*)d_in[8];
    const float* ws    = (const float*)d_in[9];
    float* out = (float*)d_out;

    static int attr_done = 0;
    if (!attr_done) {
        cudaFuncSetAttribute(rnn_prep_kernel, cudaFuncAttributeMaxDynamicSharedMemorySize, RNN_SMEM);
        cudaFuncSetAttribute(gemm_kernel, cudaFuncAttributeMaxDynamicSharedMemorySize, GEMM_SMEM);
        attr_done = 1;
    }

    rnn_prep_kernel<<<BB + NT_N, 384, RNN_SMEM>>>(users, items, h0, P_ru, W_ru, b_ru,
                                                  P_c, W_c, b_c, ws);
    gemm_kernel<<<GRID_G, 256, GEMM_SMEM>>>(out);
}

// round 13
// speedup vs baseline: 1.1611x; 1.0970x over previous
#include <cuda_runtime.h>
#include <cuda_fp16.h>
#include <cstdint>

#define BB 32
#define SS 128
#define UU 256
#define HH 128
#define VV 30001
#define NT_N 469             // 64-col image tiles (30016 cols padded)
#define NU 938               // 32-col n-units
#define NT_M 32              // m tiles of 128

__device__ __half   g_outs[BB * SS * HH];     // RNN outputs [4096][128], fp16
__device__ uint32_t g_wsB[NT_N * 4096];       // B images: fp16x2 words; unit u = words [u*2048, u*2048+2048)

// ---------------------------------------------------------------------------
__device__ __forceinline__ uint32_t smem_u32(const void* p) {
    uint32_t a;
    asm("{ .reg .u64 t; cvta.to.shared.u64 t, %1; cvt.u32.u64 %0, t; }" : "=r"(a) : "l"(p));
    return a;
}
#define CP_ASYNC16(s, g) \
    asm volatile("cp.async.cg.shared.global [%0], [%1], 16;" :: "r"(s), "l"(g) : "memory")
#define CP_COMMIT()  asm volatile("cp.async.commit_group;" ::: "memory")
#define CP_WAIT0()   asm volatile("cp.async.wait_group 0;" ::: "memory")

#define LDS128U(r0, r1, r2, r3, addr) \
    asm volatile("ld.shared.v4.u32 {%0,%1,%2,%3}, [%4];" \
                 : "=r"(r0), "=r"(r1), "=r"(r2), "=r"(r3) : "r"(addr))

__device__ __forceinline__ void mma_f16(float* d, const uint32_t* a, uint32_t b0, uint32_t b1) {
    asm volatile("mma.sync.aligned.m16n8k16.row.col.f32.f16.f16.f32 "
                 "{%0,%1,%2,%3}, {%4,%5,%6,%7}, {%8,%9}, {%0,%1,%2,%3};"
                 : "+f"(d[0]), "+f"(d[1]), "+f"(d[2]), "+f"(d[3])
                 : "r"(a[0]), "r"(a[1]), "r"(a[2]), "r"(a[3]), "r"(b0), "r"(b1));
}

// ---------------------------------------------------------------------------
// Fused kernel: CTAs [0,32) run the RNN (one per batch);
// CTAs [32, 32+469) build one 64-col pre-fragmented fp16 B tile of g_wsB.
// B image: word Wd = blk*128 + l*4 + w4, blk = nf*4 + ksp (nf 0..7, ksp 0..3).
//   fp16x2 {B[kb][n], B[kb+1][n]}, n = nf*8 + (l>>2), kb = 32*ksp + 2*(l&3) + 8*w4.
// 32-col unit u = words [u*2048, (u+1)*2048) of its tile (nf-halves contiguous).
// ---------------------------------------------------------------------------
__global__ __launch_bounds__(384, 1)
void rnn_prep_kernel(const int* __restrict__ users, const int* __restrict__ items,
                     const float* __restrict__ h0,
                     const float* __restrict__ P_ru, const float* __restrict__ W_ru,
                     const float* __restrict__ b_ru,
                     const float* __restrict__ P_c, const float* __restrict__ W_c,
                     const float* __restrict__ b_c,
                     const float* __restrict__ ws)
{
    extern __shared__ float sm[];
    const int tid = threadIdx.x;

    if (blockIdx.x >= BB) {
        const int nt = blockIdx.x - BB;
        float (*t)[65] = (float(*)[65])sm;
        const int n0 = nt * 64;

        for (int idx = tid; idx < 8192; idx += 384) {
            int k = idx >> 6, j = idx & 63;
            int n = n0 + j;
            t[k][j] = (n < VV) ? ws[(size_t)k * VV + n] : 0.f;
        }
        __syncthreads();

        uint32_t* dst = g_wsB + (size_t)nt * 4096;
        for (int Wd = tid; Wd < 4096; Wd += 384) {
            int w4  = Wd & 3;
            int l   = (Wd >> 2) & 31;
            int blk = Wd >> 7;
            int nf  = blk >> 2, ksp = blk & 3;
            int n   = nf * 8 + (l >> 2);
            int kb  = 32 * ksp + 2 * (l & 3) + 8 * w4;
            __half2 h = __floats2half2_rn(t[kb][n], t[kb + 1][n]);
            dst[Wd] = *(const uint32_t*)&h;
        }
        return;
    }

    // ---------------- RNN ----------------
    float* state_s = sm;
    float* rh_s    = sm + UU * HH;
    float* z_s     = rh_s + HH;
    int*   users_s = (int*)(z_s + HH);
    int*   items_s = users_s + SS;

    const int b = blockIdx.x;

    for (int t = tid; t < SS; t += blockDim.x) {
        users_s[t] = users[b * SS + t];
        items_s[t] = items[b * SS + t];
    }
    {
        const float4* src = (const float4*)(h0 + (size_t)b * UU * HH);
        float4* dst = (float4*)state_s;
        for (int i = tid; i < UU * HH / 4; i += blockDim.x) dst[i] = src[i];
    }

    float wreg[HH];
    float breg;
    if (tid < 2 * HH) {
        #pragma unroll
        for (int k = 0; k < HH; k++) wreg[k] = W_ru[k * (2 * HH) + tid];
        breg = b_ru[tid];
    } else {
        const int j = tid - 2 * HH;
        #pragma unroll
        for (int k = 0; k < HH; k++) wreg[k] = W_c[k * HH + j];
        breg = b_c[j];
    }
    __syncthreads();

    float pA;
    {
        int it0 = items_s[0];
        pA = (tid < 2 * HH) ? P_ru[(size_t)it0 * (2 * HH) + tid]
                            : P_c[(size_t)it0 * HH + (tid - 2 * HH)];
    }

    for (int t = 0; t < SS; t++) {
        const int u = users_s[t];
        const int itn = items_s[(t + 1) & (SS - 1)];
        float pN = (tid < 2 * HH) ? P_ru[(size_t)itn * (2 * HH) + tid]
                                  : P_c[(size_t)itn * HH + (tid - 2 * HH)];

        if (tid < 2 * HH) {
            const float* hs = state_s + u * HH;
            float a0 = 0.f, a1 = 0.f, a2 = 0.f, a3 = 0.f;
            float a4 = 0.f, a5 = 0.f, a6 = 0.f, a7 = 0.f;
            #pragma unroll
            for (int k = 0; k < HH; k += 8) {
                float4 h4 = *(const float4*)(hs + k);
                float4 h5 = *(const float4*)(hs + k + 4);
                a0 += h4.x * wreg[k];     a1 += h4.y * wreg[k + 1];
                a2 += h4.z * wreg[k + 2]; a3 += h4.w * wreg[k + 3];
                a4 += h5.x * wreg[k + 4]; a5 += h5.y * wreg[k + 5];
                a6 += h5.z * wreg[k + 6]; a7 += h5.w * wreg[k + 7];
            }
            float x = pA + breg + ((a0 + a1) + (a2 + a3)) + ((a4 + a5) + (a6 + a7));
            float sgm = 1.f / (1.f + __expf(-x));
            if (tid < HH) rh_s[tid] = sgm * hs[tid];
            else          z_s[tid - HH] = sgm;
        }
        __syncthreads();

        if (tid >= 2 * HH) {
            const int j = tid - 2 * HH;
            float a0 = 0.f, a1 = 0.f, a2 = 0.f, a3 = 0.f;
            float a4 = 0.f, a5 = 0.f, a6 = 0.f, a7 = 0.f;
            #pragma unroll
            for (int k = 0; k < HH; k += 8) {
                float4 r4 = *(const float4*)(rh_s + k);
                float4 r5 = *(const float4*)(rh_s + k + 4);
                a0 += r4.x * wreg[k];     a1 += r4.y * wreg[k + 1];
                a2 += r4.z * wreg[k + 2]; a3 += r4.w * wreg[k + 3];
                a4 += r5.x * wreg[k + 4]; a5 += r5.y * wreg[k + 5];
                a6 += r5.z * wreg[k + 6]; a7 += r5.w * wreg[k + 7];
            }
            float x = pA + breg + ((a0 + a1) + (a2 + a3)) + ((a4 + a5) + (a6 + a7));
            float c = tanhf(x);
            float h_old = state_s[u * HH + j];
            float z = z_s[j];
            float hn = z * h_old + (1.f - z) * c;
            state_s[u * HH + j] = hn;
            g_outs[((size_t)b * SS + t) * HH + j] = __float2half(hn);
        }
        __syncthreads();
        pA = pN;
    }
}

// ---------------------------------------------------------------------------
// Persistent GEMM (fp16 in, f32 acc): out[4096,30001] = g_outs @ ws
// 296 CTAs x 256 threads. Each CTA owns 3-4 32-col n-units, staged into smem
// ONCE; then loops mt = 0..31 with A reloaded per mt. ZERO in-loop barriers.
// Warp tile 16M x 32N per unit.
// ---------------------------------------------------------------------------
#define GEMM_SMEM 32768      // up to 4 units x 8KB
#define GRID_G 296

__device__ __forceinline__ void load_a(uint32_t a[8][4], int mt, int w, int l) {
    const __half* A0 = g_outs + (size_t)(mt * 128 + w * 16 + (l >> 2)) * HH;
    const __half* A1 = A0 + 8 * HH;
    #pragma unroll
    for (int ks = 0; ks < 8; ks++) {
        int k0 = 16 * ks + 2 * (l & 3);
        a[ks][0] = *(const uint32_t*)(A0 + k0);
        a[ks][1] = *(const uint32_t*)(A1 + k0);
        a[ks][2] = *(const uint32_t*)(A0 + k0 + 8);
        a[ks][3] = *(const uint32_t*)(A1 + k0 + 8);
    }
}

__global__ __launch_bounds__(256, 2)
void gemm_kernel(float* __restrict__ out)
{
    extern __shared__ uint32_t smu[];
    const int tid = threadIdx.x;
    const int w = tid >> 5, l = tid & 31;
    const uint32_t sbase = smem_u32(smu);

    const int cta = blockIdx.x;
    // 938 units = 296*3 + 50 -> first 50 CTAs take 4
    const int ustart = cta * 3 + (cta < 50 ? cta : 50);
    const int count  = 3 + (cta < 50 ? 1 : 0);

    // stage my units into smem (once)
    {
        const uint32_t* src = g_wsB + (size_t)ustart * 2048;
        const int nch = count * 512;                 // 16B chunks
        for (int ch = tid; ch < nch; ch += 256)
            CP_ASYNC16(sbase + ch * 16, src + ch * 4);
        CP_COMMIT();
        CP_WAIT0();
        __syncthreads();
    }

    const int c = l & 3, r = l >> 2;

    for (int mt = 0; mt < NT_M; mt++) {
        uint32_t a[8][4];
        load_a(a, mt, w, l);

        const size_t r0b = (size_t)(mt * 128 + w * 16 + r) * VV;
        const size_t r1b = r0b + (size_t)8 * VV;

        for (int uu = 0; uu < count; uu++) {
            const int u = ustart + uu;
            float acc[4][4];
            #pragma unroll
            for (int nf = 0; nf < 4; nf++) {
                acc[nf][0] = 0.f; acc[nf][1] = 0.f; acc[nf][2] = 0.f; acc[nf][3] = 0.f;
            }

            const uint32_t Bu = sbase + (uint32_t)uu * 8192 + (uint32_t)l * 16;
            #pragma unroll
            for (int ksp = 0; ksp < 4; ksp++) {
                uint32_t bf[4][4];
                #pragma unroll
                for (int nf = 0; nf < 4; nf++)
                    LDS128U(bf[nf][0], bf[nf][1], bf[nf][2], bf[nf][3],
                            Bu + (uint32_t)((nf * 4 + ksp) * 512));
                #pragma unroll
                for (int nf = 0; nf < 4; nf++)
                    mma_f16(acc[nf], a[2 * ksp], bf[nf][0], bf[nf][1]);
                #pragma unroll
                for (int nf = 0; nf < 4; nf++)
                    mma_f16(acc[nf], a[2 * ksp + 1], bf[nf][2], bf[nf][3]);
            }

            const int colb = u * 32 + c * 2;
            if (u != NU - 1) {
                #pragma unroll
                for (int nf = 0; nf < 4; nf++) {
                    int cc = colb + nf * 8;
                    out[r0b + cc]     = acc[nf][0];
                    out[r0b + cc + 1] = acc[nf][1];
                    out[r1b + cc]     = acc[nf][2];
                    out[r1b + cc + 1] = acc[nf][3];
                }
            } else {
                #pragma unroll
                for (int nf = 0; nf < 4; nf++) {
                    int cc = colb + nf * 8;
                    if (cc < VV)     { out[r0b + cc]     = acc[nf][0]; out[r1b + cc]     = acc[nf][2]; }
                    if (cc + 1 < VV) { out[r0b + cc + 1] = acc[nf][1]; out[r1b + cc + 1] = acc[nf][3]; }
                }
            }
        }
    }
}

// ---------------------------------------------------------------------------
#define RNN_SMEM ((UU * HH + 2 * HH) * 4 + 2 * SS * 4)

extern "C" void kernel_launch(void* const* d_in, const int* in_sizes, int n_in,
                              void* d_out, int out_size)
{
    const int*   users = (const int*)d_in[0];
    const int*   items = (const int*)d_in[1];
    const float* h0    = (const float*)d_in[2];
    const float* P_ru  = (const float*)d_in[3];
    const float* W_ru  = (const float*)d_in[4];
    const float* b_ru  = (const float*)d_in[5];
    const float* P_c   = (const float*)d_in[6];
    const float* W_c   = (const float*)d_in[7];
    const float* b_c   = (const float*)d_in[8];
    const float* ws    = (const float*)d_in[9];
    float* out = (float*)d_out;

    static int attr_done = 0;
    if (!attr_done) {
        cudaFuncSetAttribute(rnn_prep_kernel, cudaFuncAttributeMaxDynamicSharedMemorySize, RNN_SMEM);
        cudaFuncSetAttribute(gemm_kernel, cudaFuncAttributeMaxDynamicSharedMemorySize, GEMM_SMEM);
        attr_done = 1;
    }

    rnn_prep_kernel<<<BB + NT_N, 384, RNN_SMEM>>>(users, items, h0, P_ru, W_ru, b_ru,
                                                  P_c, W_c, b_c, ws);
    gemm_kernel<<<GRID_G, 256, GEMM_SMEM>>>(out);
}

// round 15
// speedup vs baseline: 1.4937x; 1.2865x over previous
#include <cuda_runtime.h>
#include <cuda_fp16.h>
#include <cstdint>

#define BB 32
#define SS 128
#define UU 256
#define HH 128
#define VV 30001
#define NT_N 469             // 64-col image tiles (30016 cols padded)
#define NU 938               // 32-col n-units
#define NT_M 32              // m tiles of 128

__device__ __half   g_outs[BB * SS * HH];     // RNN outputs [4096][128], fp16
__device__ uint32_t g_wsB[NT_N * 4096];       // B images: fp16x2 words; unit u = words [u*2048, u*2048+2048)

// ---------------------------------------------------------------------------
__device__ __forceinline__ uint32_t smem_u32(const void* p) {
    uint32_t a;
    asm("{ .reg .u64 t; cvta.to.shared.u64 t, %1; cvt.u32.u64 %0, t; }" : "=r"(a) : "l"(p));
    return a;
}
#define CP_ASYNC16(s, g) \
    asm volatile("cp.async.cg.shared.global [%0], [%1], 16;" :: "r"(s), "l"(g) : "memory")
#define CP_COMMIT()  asm volatile("cp.async.commit_group;" ::: "memory")
#define CP_WAIT0()   asm volatile("cp.async.wait_group 0;" ::: "memory")

#define LDS128U(r0, r1, r2, r3, addr) \
    asm volatile("ld.shared.v4.u32 {%0,%1,%2,%3}, [%4];" \
                 : "=r"(r0), "=r"(r1), "=r"(r2), "=r"(r3) : "r"(addr))

__device__ __forceinline__ void mma_f16(float* d, const uint32_t* a, uint32_t b0, uint32_t b1) {
    asm volatile("mma.sync.aligned.m16n8k16.row.col.f32.f16.f16.f32 "
                 "{%0,%1,%2,%3}, {%4,%5,%6,%7}, {%8,%9}, {%0,%1,%2,%3};"
                 : "+f"(d[0]), "+f"(d[1]), "+f"(d[2]), "+f"(d[3])
                 : "r"(a[0]), "r"(a[1]), "r"(a[2]), "r"(a[3]), "r"(b0), "r"(b1));
}

// ---------------------------------------------------------------------------
// Fused kernel: CTAs [0,32) run the RNN (one per batch);
// CTAs [32, 32+469) build one 64-col pre-fragmented fp16 B tile of g_wsB.
// B image: word Wd = blk*128 + l*4 + w4, blk = nf*4 + ksp.
//   fp16x2 {B[kb][n], B[kb+1][n]}, n = nf*8 + (l>>2), kb = 32*ksp + 2*(l&3) + 8*w4.
// ---------------------------------------------------------------------------
__global__ __launch_bounds__(384, 1)
void rnn_prep_kernel(const int* __restrict__ users, const int* __restrict__ items,
                     const float* __restrict__ h0,
                     const float* __restrict__ P_ru, const float* __restrict__ W_ru,
                     const float* __restrict__ b_ru,
                     const float* __restrict__ P_c, const float* __restrict__ W_c,
                     const float* __restrict__ b_c,
                     const float* __restrict__ ws)
{
    extern __shared__ float sm[];
    const int tid = threadIdx.x;

    if (blockIdx.x >= BB) {
        const int nt = blockIdx.x - BB;
        float (*t)[65] = (float(*)[65])sm;
        const int n0 = nt * 64;

        for (int idx = tid; idx < 8192; idx += 384) {
            int k = idx >> 6, j = idx & 63;
            int n = n0 + j;
            t[k][j] = (n < VV) ? ws[(size_t)k * VV + n] : 0.f;
        }
        __syncthreads();

        uint32_t* dst = g_wsB + (size_t)nt * 4096;
        for (int Wd = tid; Wd < 4096; Wd += 384) {
            int w4  = Wd & 3;
            int l   = (Wd >> 2) & 31;
            int blk = Wd >> 7;
            int nf  = blk >> 2, ksp = blk & 3;
            int n   = nf * 8 + (l >> 2);
            int kb  = 32 * ksp + 2 * (l & 3) + 8 * w4;
            __half2 h = __floats2half2_rn(t[kb][n], t[kb + 1][n]);
            dst[Wd] = *(const uint32_t*)&h;
        }
        return;
    }

    // ---------------- RNN ----------------
    float* state_s = sm;
    float* rh_s    = sm + UU * HH;
    float* z_s     = rh_s + HH;
    int*   users_s = (int*)(z_s + HH);
    int*   items_s = users_s + SS;

    const int b = blockIdx.x;

    for (int t = tid; t < SS; t += blockDim.x) {
        users_s[t] = users[b * SS + t];
        items_s[t] = items[b * SS + t];
    }
    {
        const float4* src = (const float4*)(h0 + (size_t)b * UU * HH);
        float4* dst = (float4*)state_s;
        for (int i = tid; i < UU * HH / 4; i += blockDim.x) dst[i] = src[i];
    }

    float wreg[HH];
    float breg;
    if (tid < 2 * HH) {
        #pragma unroll
        for (int k = 0; k < HH; k++) wreg[k] = W_ru[k * (2 * HH) + tid];
        breg = b_ru[tid];
    } else {
        const int j = tid - 2 * HH;
        #pragma unroll
        for (int k = 0; k < HH; k++) wreg[k] = W_c[k * HH + j];
        breg = b_c[j];
    }
    __syncthreads();

    float pA;
    {
        int it0 = items_s[0];
        pA = (tid < 2 * HH) ? P_ru[(size_t)it0 * (2 * HH) + tid]
                            : P_c[(size_t)it0 * HH + (tid - 2 * HH)];
    }

    for (int t = 0; t < SS; t++) {
        const int u = users_s[t];
        const int itn = items_s[(t + 1) & (SS - 1)];
        float pN = (tid < 2 * HH) ? P_ru[(size_t)itn * (2 * HH) + tid]
                                  : P_c[(size_t)itn * HH + (tid - 2 * HH)];

        if (tid < 2 * HH) {
            const float* hs = state_s + u * HH;
            float a0 = 0.f, a1 = 0.f, a2 = 0.f, a3 = 0.f;
            float a4 = 0.f, a5 = 0.f, a6 = 0.f, a7 = 0.f;
            #pragma unroll
            for (int k = 0; k < HH; k += 8) {
                float4 h4 = *(const float4*)(hs + k);
                float4 h5 = *(const float4*)(hs + k + 4);
                a0 += h4.x * wreg[k];     a1 += h4.y * wreg[k + 1];
                a2 += h4.z * wreg[k + 2]; a3 += h4.w * wreg[k + 3];
                a4 += h5.x * wreg[k + 4]; a5 += h5.y * wreg[k + 5];
                a6 += h5.z * wreg[k + 6]; a7 += h5.w * wreg[k + 7];
            }
            float x = pA + breg + ((a0 + a1) + (a2 + a3)) + ((a4 + a5) + (a6 + a7));
            float sgm = 1.f / (1.f + __expf(-x));
            if (tid < HH) rh_s[tid] = sgm * hs[tid];
            else          z_s[tid - HH] = sgm;
        }
        __syncthreads();

        if (tid >= 2 * HH) {
            const int j = tid - 2 * HH;
            float a0 = 0.f, a1 = 0.f, a2 = 0.f, a3 = 0.f;
            float a4 = 0.f, a5 = 0.f, a6 = 0.f, a7 = 0.f;
            #pragma unroll
            for (int k = 0; k < HH; k += 8) {
                float4 r4 = *(const float4*)(rh_s + k);
                float4 r5 = *(const float4*)(rh_s + k + 4);
                a0 += r4.x * wreg[k];     a1 += r4.y * wreg[k + 1];
                a2 += r4.z * wreg[k + 2]; a3 += r4.w * wreg[k + 3];
                a4 += r5.x * wreg[k + 4]; a5 += r5.y * wreg[k + 5];
                a6 += r5.z * wreg[k + 6]; a7 += r5.w * wreg[k + 7];
            }
            float x = pA + breg + ((a0 + a1) + (a2 + a3)) + ((a4 + a5) + (a6 + a7));
            float c = tanhf(x);
            float h_old = state_s[u * HH + j];
            float z = z_s[j];
            float hn = z * h_old + (1.f - z) * c;
            state_s[u * HH + j] = hn;
            g_outs[((size_t)b * SS + t) * HH + j] = __float2half(hn);
        }
        __syncthreads();
        pA = pN;
    }
}

// ---------------------------------------------------------------------------
// Persistent GEMM (fp16 in, f32 acc): out[4096,30001] = g_outs @ ws
// 296 CTAs x 256 threads. Each CTA owns 3-4 32-col n-units (B smem-resident).
// Per mt: A tile cp.async'd into padded smem (272B row stride -> conflict-free
// fragment LDS), A(mt+1) prefetch overlaps compute. Epilogue goes through a
// column-major smem buffer (stride 137 words) so gmem stores are row-coalesced.
// ---------------------------------------------------------------------------
#define SM_A_OFF  0          // 128 rows * 272 B = 34816
#define SM_B_OFF  34816      // up to 4 units * 8192 = 32768
#define SM_C_OFF  67584      // 32 cols * 137 words * 4 B = 17536
#define GEMM_SMEM 85120
#define GRID_G 296

__global__ __launch_bounds__(256, 2)
void gemm_kernel(float* __restrict__ out)
{
    extern __shared__ uint32_t smu[];
    const int tid = threadIdx.x;
    const int w = tid >> 5, l = tid & 31;
    const uint32_t sbase = smem_u32(smu);
    const int c = l & 3, r = l >> 2;

    const int cta = blockIdx.x;
    // 938 units = 296*3 + 50 -> first 50 CTAs take 4
    const int ustart = cta * 3 + (cta < 50 ? cta : 50);
    const int count  = 3 + (cta < 50 ? 1 : 0);

    const uint32_t* smA = smu;                       // word view of A
    float* Cs = (float*)(smu + SM_C_OFF / 4);        // [32 cols][137 words]

    // prologue: stage B units + A(0), one group
    {
        const uint32_t* srcB = g_wsB + (size_t)ustart * 2048;
        const int nch = count * 512;
        for (int ch = tid; ch < nch; ch += 256)
            CP_ASYNC16(sbase + SM_B_OFF + ch * 16, srcB + ch * 4);
        const char* srcA = (const char*)g_outs;      // mt=0 tile, linear 32KB
        #pragma unroll
        for (int j = 0; j < 8; j++) {
            int ch = tid + j * 256;                  // 2048 chunks of 16B
            CP_ASYNC16(sbase + SM_A_OFF + (ch >> 4) * 272 + (ch & 15) * 16,
                       srcA + ch * 16);
        }
        CP_COMMIT();
        CP_WAIT0();
        __syncthreads();
    }

    for (int mt = 0; mt < NT_M; mt++) {
        if (mt > 0) {            // A(mt) group issued last iteration
            CP_WAIT0();
            __syncthreads();
        }

        // A fragments from smem (conflict-free: bank = 4r + c + 8ks)
        uint32_t a[8][4];
        {
            const int w0 = (w * 16 + r) * 68 + c;
            #pragma unroll
            for (int ks = 0; ks < 8; ks++) {
                int b0 = w0 + 8 * ks;
                a[ks][0] = smA[b0];
                a[ks][1] = smA[b0 + 544];        // row + 8
                a[ks][2] = smA[b0 + 4];          // k + 8 halfs
                a[ks][3] = smA[b0 + 548];
            }
        }
        __syncthreads();         // all warps done reading A(mt)

        if (mt + 1 < NT_M) {     // prefetch A(mt+1), overlapped with compute
            const char* srcA = (const char*)g_outs + (size_t)(mt + 1) * 32768;
            #pragma unroll
            for (int j = 0; j < 8; j++) {
                int ch = tid + j * 256;
                CP_ASYNC16(sbase + SM_A_OFF + (ch >> 4) * 272 + (ch & 15) * 16,
                           srcA + ch * 16);
            }
            CP_COMMIT();
        }

        for (int uu = 0; uu < count; uu++) {
            const int u = ustart + uu;
            float acc[4][4];
            #pragma unroll
            for (int nf = 0; nf < 4; nf++) {
                acc[nf][0] = 0.f; acc[nf][1] = 0.f; acc[nf][2] = 0.f; acc[nf][3] = 0.f;
            }

            const uint32_t Bu = sbase + SM_B_OFF + (uint32_t)uu * 8192 + (uint32_t)l * 16;
            #pragma unroll
            for (int ksp = 0; ksp < 4; ksp++) {
                uint32_t bf[4][4];
                #pragma unroll
                for (int nf = 0; nf < 4; nf++)
                    LDS128U(bf[nf][0], bf[nf][1], bf[nf][2], bf[nf][3],
                            Bu + (uint32_t)((nf * 4 + ksp) * 512));
                #pragma unroll
                for (int nf = 0; nf < 4; nf++)
                    mma_f16(acc[nf], a[2 * ksp], bf[nf][0], bf[nf][1]);
                #pragma unroll
                for (int nf = 0; nf < 4; nf++)
                    mma_f16(acc[nf], a[2 * ksp + 1], bf[nf][2], bf[nf][3]);
            }

            // epilogue: acc -> Cs (column-major, stride 137) -> coalesced gmem
            {
                const int row0 = w * 16 + r;
                #pragma unroll
                for (int nf = 0; nf < 4; nf++) {
                    int c0 = (c * 2 + nf * 8) * 137;
                    Cs[c0 + row0]             = acc[nf][0];
                    Cs[c0 + 137 + row0]       = acc[nf][1];
                    Cs[c0 + row0 + 8]         = acc[nf][2];
                    Cs[c0 + 137 + row0 + 8]   = acc[nf][3];
                }
            }
            __syncthreads();
            {
                const int gcol = u * 32 + l;
                if (u != NU - 1) {
                    #pragma unroll
                    for (int i = 0; i < 16; i++) {
                        int row = 8 * i + w;
                        out[(size_t)(mt * 128 + row) * VV + gcol] = Cs[l * 137 + row];
                    }
                } else if (gcol < VV) {
                    #pragma unroll
                    for (int i = 0; i < 16; i++) {
                        int row = 8 * i + w;
                        out[(size_t)(mt * 128 + row) * VV + gcol] = Cs[l * 137 + row];
                    }
                }
            }
            __syncthreads();
        }
    }
}

// ---------------------------------------------------------------------------
#define RNN_SMEM ((UU * HH + 2 * HH) * 4 + 2 * SS * 4)

extern "C" void kernel_launch(void* const* d_in, const int* in_sizes, int n_in,
                              void* d_out, int out_size)
{
    const int*   users = (const int*)d_in[0];
    const int*   items = (const int*)d_in[1];
    const float* h0    = (const float*)d_in[2];
    const float* P_ru  = (const float*)d_in[3];
    const float* W_ru  = (const float*)d_in[4];
    const float* b_ru  = (const float*)d_in[5];
    const float* P_c   = (const float*)d_in[6];
    const float* W_c   = (const float*)d_in[7];
    const float* b_c   = (const float*)d_in[8];
    const float* ws    = (const float*)d_in[9];
    float* out = (float*)d_out;

    static int attr_done = 0;
    if (!attr_done) {
        cudaFuncSetAttribute(rnn_prep_kernel, cudaFuncAttributeMaxDynamicSharedMemorySize, RNN_SMEM);
        cudaFuncSetAttribute(gemm_kernel, cudaFuncAttributeMaxDynamicSharedMemorySize, GEMM_SMEM);
        attr_done = 1;
    }

    rnn_prep_kernel<<<BB + NT_N, 384, RNN_SMEM>>>(users, items, h0, P_ru, W_ru, b_ru,
                                                  P_c, W_c, b_c, ws);
    gemm_kernel<<<GRID_G, 256, GEMM_SMEM>>>(out);
}